// round 4
// baseline (speedup 1.0000x reference)
#include <cuda_runtime.h>

#define N_NODES 50000
#define N_EDGES 200000
#define IN_F 32
#define HID 32
#define N_GRAPHS 64
#define NBINS 65
#define EB 256                 // edges per block
#define NEBLK ((N_EDGES + EB - 1) / EB)

// ---------------- scratch (no allocs allowed) ----------------
__device__ float g_agg[N_NODES * HID];
__device__ float g_cnt[N_NODES];
__device__ float g_gsum[N_GRAPHS * HID];
__device__ float g_gcnt[N_GRAPHS];
__device__ float g_P[NBINS * 1024];
__device__ float g_Q[NBINS * 1024];
__device__ int   g_hist[NBINS];
__device__ int   g_coff[NBINS];
__device__ int   g_s[N_EDGES];
__device__ int   g_perm[N_EDGES];

__device__ __forceinline__ float inf_f() { return __int_as_float(0x7f800000); }

// key_j: breakpoint of relu(a*w1_j + b1_j); +inf if no crossing possible (w==0)
__device__ __forceinline__ float key_of(float w, float b) {
    return (w != 0.f) ? (-b / w) : inf_f();
}

// ---------------- K0: zero scratch ----------------
__global__ void zero_kernel() {
    int idx = blockIdx.x * blockDim.x + threadIdx.x;
    int stride = gridDim.x * blockDim.x;
    for (int i = idx; i < N_NODES * HID; i += stride) g_agg[i] = 0.f;
    for (int i = idx; i < N_NODES; i += stride) g_cnt[i] = 0.f;
    if (idx < N_GRAPHS * HID) g_gsum[idx] = 0.f;
    if (idx < N_GRAPHS) g_gcnt[idx] = 0.f;
    if (idx < NBINS) { g_hist[idx] = 0; g_coff[idx] = 0; }
}

// ---------------- K1: build per-interval matrices P_s, Q_s ----------------
// bin s = (count of keys < a). Interval boundaries = s-th order stats of keys.
__global__ void __launch_bounds__(256) build_kernel(
    const float* __restrict__ w1, const float* __restrict__ b1,
    const float* __restrict__ w2, const float* __restrict__ b2)
{
    __shared__ float key[64], srt[64], wa[64], ba[64];
    const int t = threadIdx.x;
    const int s = blockIdx.x;

    if (t < 64) key[t] = key_of(w1[t], b1[t]);
    __syncthreads();
    if (t < 64) {
        float kt = key[t];
        int r = 0;
        #pragma unroll
        for (int k = 0; k < 64; k++) {
            float kk = key[k];
            r += (kk < kt) || (kk == kt && k < t);
        }
        srt[r] = kt;
    }
    __syncthreads();

    float lo = (s == 0)     ? 0.f : fminf(fmaxf(srt[s - 1], 0.f), 1.f);
    float hi = (s == NBINS - 1) ? 1.f : fminf(fmaxf(srt[s], 0.f), 1.f);
    float m  = 0.5f * (lo + hi);

    if (t < 64) {
        float w = w1[t], b = b1[t];
        bool act = (fmaf(m, w, b) > 0.f);
        wa[t] = act ? w : 0.f;
        ba[t] = act ? b : 0.f;
    }
    __syncthreads();

    for (int e = t; e < 1024; e += 256) {
        float p = 0.f, q = 0.f;
        #pragma unroll 8
        for (int j = 0; j < 64; j++) {
            float v = w2[j * 1024 + e];
            p = fmaf(wa[j], v, p);
            q = fmaf(ba[j], v, q);
        }
        g_P[s * 1024 + e] = p;
        g_Q[s * 1024 + e] = q + b2[e];
    }
}

// ---------------- K2: per-edge bin id + histogram + degree count ----------------
__global__ void __launch_bounds__(256) hist_kernel(
    const float* __restrict__ ea, const int* __restrict__ ei,
    const float* __restrict__ w1, const float* __restrict__ b1)
{
    __shared__ float key[64];
    __shared__ int lh[NBINS];
    const int t = threadIdx.x;
    if (t < 64) key[t] = key_of(w1[t], b1[t]);
    if (t < NBINS) lh[t] = 0;
    __syncthreads();

    int e = blockIdx.x * EB + t;
    if (e < N_EDGES) {
        float a = ea[e];
        int s = 0;
        #pragma unroll 16
        for (int k = 0; k < 64; k++) s += (key[k] < a) ? 1 : 0;
        g_s[e] = s;
        atomicAdd(&lh[s], 1);
        atomicAdd(&g_cnt[ei[N_EDGES + e]], 1.f);
    }
    __syncthreads();
    if (t < NBINS && lh[t]) atomicAdd(&g_hist[t], lh[t]);
}

// ---------------- K3: scatter into bin-sorted permutation ----------------
__global__ void __launch_bounds__(256) scatter_kernel()
{
    __shared__ int start[NBINS];
    const int t = threadIdx.x;
    if (t == 0) {
        int acc = 0;
        for (int i = 0; i < NBINS; i++) { start[i] = acc; acc += g_hist[i]; }
    }
    __syncthreads();
    int e = blockIdx.x * EB + t;
    if (e < N_EDGES) {
        int s = g_s[e];
        int pos = start[s] + atomicAdd(&g_coff[s], 1);
        g_perm[pos] = e;
    }
}

// ---------------- K4: edge messages (fp32, table-based) ----------------
// msg_e = a_e * (x_src @ P_s) + (x_src @ Q_s)
__global__ void __launch_bounds__(256) edge2_kernel(
    const float* __restrict__ x, const int* __restrict__ ei,
    const float* __restrict__ ea)
{
    __shared__ float4 sP[256], sQ[256];   // 32x32 each, row i -> [i*8 .. i*8+7]
    const int t = threadIdx.x;
    const int base = blockIdx.x * EB;
    const int idx = base + t;
    const bool v = (idx < N_EDGES);

    int e = g_perm[v ? idx : (N_EDGES - 1)];
    const int s_t = g_s[e];
    const int endidx = min(base + EB - 1, N_EDGES - 1);
    const int s_lo = g_s[g_perm[base]];
    const int s_hi = g_s[g_perm[endidx]];

    const int src = ei[e];
    const int dst = ei[N_EDGES + e];
    const float a = ea[e];

    float xr[32];
    {
        const float4* xp = (const float4*)(x + src * IN_F);
        #pragma unroll
        for (int u = 0; u < 8; u++) {
            float4 f = xp[u];
            xr[4 * u] = f.x; xr[4 * u + 1] = f.y;
            xr[4 * u + 2] = f.z; xr[4 * u + 3] = f.w;
        }
    }

    for (int s = s_lo; s <= s_hi; s++) {
        bool mine = v && (s_t == s);
        if (!__syncthreads_or(mine ? 1 : 0)) continue;
        // stage P_s, Q_s (broadcast-read later)
        const float4* gp = (const float4*)(g_P + s * 1024);
        const float4* gq = (const float4*)(g_Q + s * 1024);
        if (t < 256) { sP[t] = gp[t]; sQ[t] = gq[t]; }
        __syncthreads();
        if (mine) {
            float* aggp = &g_agg[dst * HID];
            #pragma unroll
            for (int nc = 0; nc < 8; nc++) {
                float ux = 0.f, uy = 0.f, uz = 0.f, uw = 0.f;
                float qx = 0.f, qy = 0.f, qz = 0.f, qw = 0.f;
                #pragma unroll 8
                for (int i = 0; i < 32; i++) {
                    float xi = xr[i];
                    float4 pv = sP[i * 8 + nc];
                    float4 qv = sQ[i * 8 + nc];
                    ux = fmaf(xi, pv.x, ux); uy = fmaf(xi, pv.y, uy);
                    uz = fmaf(xi, pv.z, uz); uw = fmaf(xi, pv.w, uw);
                    qx = fmaf(xi, qv.x, qx); qy = fmaf(xi, qv.y, qy);
                    qz = fmaf(xi, qv.z, qz); qw = fmaf(xi, qv.w, qw);
                }
                atomicAdd(aggp + nc * 4 + 0, fmaf(a, ux, qx));
                atomicAdd(aggp + nc * 4 + 1, fmaf(a, uy, qy));
                atomicAdd(aggp + nc * 4 + 2, fmaf(a, uz, qz));
                atomicAdd(aggp + nc * 4 + 3, fmaf(a, uw, qw));
            }
        }
        __syncthreads();
    }
}

// ---------------- K5: node update + graph pooling ----------------
__global__ void __launch_bounds__(256) node_kernel(
    const float* __restrict__ x, const int* __restrict__ batch,
    const float* __restrict__ root, const float* __restrict__ conv_bias)
{
    int wrp = threadIdx.x >> 5, lane = threadIdx.x & 31;
    int n = blockIdx.x * 8 + wrp;
    if (n >= N_NODES) return;
    float vv = g_agg[n * HID + lane];
    float c = g_cnt[n];
    vv /= fmaxf(c, 1.f);
    float xv = x[n * IN_F + lane];
    float ss = 0.f;
    #pragma unroll
    for (int i = 0; i < IN_F; i++) {
        float xi = __shfl_sync(0xffffffffu, xv, i);
        ss = fmaf(xi, root[i * HID + lane], ss);
    }
    vv = fmaxf(vv + ss + conv_bias[lane], 0.f);
    int g = batch[n];
    atomicAdd(&g_gsum[g * HID + lane], vv);
    if (lane == 0) atomicAdd(&g_gcnt[g], 1.f);
}

// ---------------- K6: classifier ----------------
__global__ void final_kernel(const float* __restrict__ lin_w,
                             const float* __restrict__ lin_b,
                             float* __restrict__ out)
{
    int t = threadIdx.x;
    if (t >= N_GRAPHS * 2) return;
    int g = t >> 1, c = t & 1;
    float cnt = fmaxf(g_gcnt[g], 1.f);
    float s = 0.f;
    #pragma unroll
    for (int h = 0; h < HID; h++)
        s += g_gsum[g * HID + h] * lin_w[h * 2 + c];
    out[g * 2 + c] = s / cnt + lin_b[c];
}

// ---------------- launcher ----------------
extern "C" void kernel_launch(void* const* d_in, const int* in_sizes, int n_in,
                              void* d_out, int out_size) {
    const float* x    = (const float*)d_in[0];
    const int*   ei   = (const int*)  d_in[1];
    const float* ea   = (const float*)d_in[2];
    const int*   bat  = (const int*)  d_in[3];
    const float* w1   = (const float*)d_in[4];
    const float* b1   = (const float*)d_in[5];
    const float* w2   = (const float*)d_in[6];
    const float* b2   = (const float*)d_in[7];
    const float* root = (const float*)d_in[8];
    const float* cb   = (const float*)d_in[9];
    const float* lw   = (const float*)d_in[10];
    const float* lb   = (const float*)d_in[11];
    float* out = (float*)d_out;

    zero_kernel<<<512, 256>>>();
    build_kernel<<<NBINS, 256>>>(w1, b1, w2, b2);
    hist_kernel<<<NEBLK, 256>>>(ea, ei, w1, b1);
    scatter_kernel<<<NEBLK, 256>>>();
    edge2_kernel<<<NEBLK, 256>>>(x, ei, ea);
    node_kernel<<<(N_NODES + 7) / 8, 256>>>(x, bat, root, cb);
    final_kernel<<<1, 128>>>(lw, lb, out);
}

// round 5
// speedup vs baseline: 1.4575x; 1.4575x over previous
#include <cuda_runtime.h>

#define N_NODES 50000
#define N_EDGES 200000
#define IN_F 32
#define HID 32
#define N_GRAPHS 64
#define NBINS 65
#define EB 256                 // edges per block
#define NEBLK ((N_EDGES + EB - 1) / EB)

// ---------------- scratch (no allocs allowed) ----------------
__device__ float g_agg[N_NODES * HID];
__device__ float g_cnt[N_NODES];
__device__ float g_gsum[N_GRAPHS * HID];
__device__ float g_gcnt[N_GRAPHS];
__device__ float g_P[NBINS * 1024];
__device__ float g_Q[NBINS * 1024];
__device__ int   g_bhist[NBINS * NEBLK];
__device__ int   g_sr[N_EDGES];      // s | (local_rank << 8)
__device__ int   g_perm[N_EDGES];    // e | (s << 18)

__device__ __forceinline__ float inf_f() { return __int_as_float(0x7f800000); }

__device__ __forceinline__ float key_of(float w, float b) {
    return (w != 0.f) ? (-b / w) : inf_f();
}

__device__ __forceinline__ void red_add_v4(float* p, float a, float b, float c, float d) {
    asm volatile("red.global.add.v4.f32 [%0], {%1,%2,%3,%4};"
                 :: "l"(p), "f"(a), "f"(b), "f"(c), "f"(d) : "memory");
}

// ---------------- K0: zero scratch ----------------
__global__ void zero_kernel() {
    int idx = blockIdx.x * blockDim.x + threadIdx.x;
    int stride = gridDim.x * blockDim.x;
    float4 z = make_float4(0.f, 0.f, 0.f, 0.f);
    float4* aggp = (float4*)g_agg;
    for (int i = idx; i < N_NODES * HID / 4; i += stride) aggp[i] = z;
    for (int i = idx; i < N_NODES; i += stride) g_cnt[i] = 0.f;
    if (idx < N_GRAPHS * HID) g_gsum[idx] = 0.f;
    if (idx < N_GRAPHS) g_gcnt[idx] = 0.f;
}

// ---------------- K1: build per-interval matrices P_s, Q_s ----------------
__global__ void __launch_bounds__(256) build_kernel(
    const float* __restrict__ w1, const float* __restrict__ b1,
    const float* __restrict__ w2, const float* __restrict__ b2)
{
    __shared__ float key[64], srt[64], wa[64], ba[64];
    const int t = threadIdx.x;
    const int s = blockIdx.x;

    if (t < 64) key[t] = key_of(w1[t], b1[t]);
    __syncthreads();
    if (t < 64) {
        float kt = key[t];
        int r = 0;
        #pragma unroll
        for (int k = 0; k < 64; k++) {
            float kk = key[k];
            r += (kk < kt) || (kk == kt && k < t);
        }
        srt[r] = kt;
    }
    __syncthreads();

    float lo = (s == 0)         ? 0.f : fminf(fmaxf(srt[s - 1], 0.f), 1.f);
    float hi = (s == NBINS - 1) ? 1.f : fminf(fmaxf(srt[s], 0.f), 1.f);
    float m  = 0.5f * (lo + hi);

    if (t < 64) {
        float w = w1[t], b = b1[t];
        bool act = (fmaf(m, w, b) > 0.f);
        wa[t] = act ? w : 0.f;
        ba[t] = act ? b : 0.f;
    }
    __syncthreads();

    for (int e = t; e < 1024; e += 256) {
        float p = 0.f, q = 0.f;
        #pragma unroll 8
        for (int j = 0; j < 64; j++) {
            float v = w2[j * 1024 + e];
            p = fmaf(wa[j], v, p);
            q = fmaf(ba[j], v, q);
        }
        g_P[s * 1024 + e] = p;
        g_Q[s * 1024 + e] = q + b2[e];
    }
}

// ---------------- K2: bin id + local rank + per-block hist + degrees ----------------
__global__ void __launch_bounds__(256) hist_kernel(
    const float* __restrict__ ea, const int* __restrict__ ei,
    const float* __restrict__ w1, const float* __restrict__ b1)
{
    __shared__ float key[64];
    __shared__ int lh[NBINS];
    const int t = threadIdx.x;
    if (t < 64) key[t] = key_of(w1[t], b1[t]);
    if (t < NBINS) lh[t] = 0;
    __syncthreads();

    int e = blockIdx.x * EB + t;
    if (e < N_EDGES) {
        float a = ea[e];
        int s = 0;
        #pragma unroll 16
        for (int k = 0; k < 64; k++) s += (key[k] < a) ? 1 : 0;
        int r = atomicAdd(&lh[s], 1);
        g_sr[e] = s | (r << 8);
        atomicAdd(&g_cnt[ei[N_EDGES + e]], 1.f);
    }
    __syncthreads();
    if (t < NBINS) g_bhist[t * NEBLK + blockIdx.x] = lh[t];
}

// ---------------- K3: exclusive scan over g_bhist (single block) ----------------
__global__ void __launch_bounds__(1024) prefix_kernel()
{
    __shared__ int ssum[1024];
    const int NTOT = NBINS * NEBLK;
    const int C = (NTOT + 1023) / 1024;
    int t = threadIdx.x;
    int beg = t * C, end = min(beg + C, NTOT);
    int s = 0;
    for (int i = beg; i < end; i++) s += g_bhist[i];
    ssum[t] = s;
    __syncthreads();
    for (int d = 1; d < 1024; d <<= 1) {
        int v = (t >= d) ? ssum[t - d] : 0;
        __syncthreads();
        ssum[t] += v;
        __syncthreads();
    }
    int carry = (t > 0) ? ssum[t - 1] : 0;
    for (int i = beg; i < end; i++) {
        int v = g_bhist[i];
        g_bhist[i] = carry;
        carry += v;
    }
}

// ---------------- K4: deterministic scatter (no atomics) ----------------
__global__ void __launch_bounds__(256) scatter_kernel()
{
    int e = blockIdx.x * EB + threadIdx.x;
    if (e < N_EDGES) {
        int sr = g_sr[e];
        int s = sr & 0xFF, r = sr >> 8;
        int pos = g_bhist[s * NEBLK + blockIdx.x] + r;
        g_perm[pos] = e | (s << 18);
    }
}

// ---------------- K5: edge messages (fp32, table-based) ----------------
// msg_e = a_e * (x_src @ P_s) + (x_src @ Q_s)
__global__ void __launch_bounds__(256) edge2_kernel(
    const float* __restrict__ x, const int* __restrict__ ei,
    const float* __restrict__ ea)
{
    __shared__ float4 sP[256], sQ[256];   // 32x32 each, row i -> [i*8 .. i*8+7]
    const int t = threadIdx.x;
    const int base = blockIdx.x * EB;
    const int idx = base + t;
    const bool v = (idx < N_EDGES);

    const int endidx = min(base + EB - 1, N_EDGES - 1);
    int pk   = g_perm[v ? idx : endidx];
    const int e   = pk & 0x3FFFF;
    const int s_t = pk >> 18;
    const int s_lo = g_perm[base] >> 18;
    const int s_hi = g_perm[endidx] >> 18;

    const int src = ei[e];
    const int dst = ei[N_EDGES + e];
    const float a = ea[e];

    float xr[32];
    {
        const float4* xp = (const float4*)(x + src * IN_F);
        #pragma unroll
        for (int u = 0; u < 8; u++) {
            float4 f = xp[u];
            xr[4 * u] = f.x; xr[4 * u + 1] = f.y;
            xr[4 * u + 2] = f.z; xr[4 * u + 3] = f.w;
        }
    }

    for (int s = s_lo; s <= s_hi; s++) {
        bool mine = v && (s_t == s);
        if (!__syncthreads_or(mine ? 1 : 0)) continue;
        const float4* gp = (const float4*)(g_P + s * 1024);
        const float4* gq = (const float4*)(g_Q + s * 1024);
        sP[t] = gp[t]; sQ[t] = gq[t];
        __syncthreads();
        if (mine) {
            float* aggp = &g_agg[dst * HID];
            #pragma unroll
            for (int nc = 0; nc < 8; nc++) {
                float ux = 0.f, uy = 0.f, uz = 0.f, uw = 0.f;
                float qx = 0.f, qy = 0.f, qz = 0.f, qw = 0.f;
                #pragma unroll 8
                for (int i = 0; i < 32; i++) {
                    float xi = xr[i];
                    float4 pv = sP[i * 8 + nc];
                    float4 qv = sQ[i * 8 + nc];
                    ux = fmaf(xi, pv.x, ux); uy = fmaf(xi, pv.y, uy);
                    uz = fmaf(xi, pv.z, uz); uw = fmaf(xi, pv.w, uw);
                    qx = fmaf(xi, qv.x, qx); qy = fmaf(xi, qv.y, qy);
                    qz = fmaf(xi, qv.z, qz); qw = fmaf(xi, qv.w, qw);
                }
                red_add_v4(aggp + nc * 4,
                           fmaf(a, ux, qx), fmaf(a, uy, qy),
                           fmaf(a, uz, qz), fmaf(a, uw, qw));
            }
        }
        __syncthreads();
    }
}

// ---------------- K6: node update + graph pooling (run-length flush) ----------------
__global__ void __launch_bounds__(256) node_kernel(
    const float* __restrict__ x, const int* __restrict__ batch,
    const float* __restrict__ root, const float* __restrict__ conv_bias)
{
    int wrp = threadIdx.x >> 5, lane = threadIdx.x & 31;
    int n0 = (blockIdx.x * 8 + wrp) * 8;
    if (n0 >= N_NODES) return;

    float rt[32];
    #pragma unroll
    for (int i = 0; i < IN_F; i++) rt[i] = root[i * HID + lane];
    const float cb = conv_bias[lane];

    float acc = 0.f, ccnt = 0.f;
    int gcur = batch[n0];
    #pragma unroll
    for (int k = 0; k < 8; k++) {
        int n = n0 + k;
        if (n >= N_NODES) break;
        int g = batch[n];
        if (g != gcur) {
            atomicAdd(&g_gsum[gcur * HID + lane], acc);
            if (lane == 0) atomicAdd(&g_gcnt[gcur], ccnt);
            acc = 0.f; ccnt = 0.f; gcur = g;
        }
        float vv = g_agg[n * HID + lane] / fmaxf(g_cnt[n], 1.f);
        float xv = x[n * IN_F + lane];
        float ss = 0.f;
        #pragma unroll
        for (int i = 0; i < IN_F; i++)
            ss = fmaf(__shfl_sync(0xffffffffu, xv, i), rt[i], ss);
        acc += fmaxf(vv + ss + cb, 0.f);
        ccnt += 1.f;
    }
    atomicAdd(&g_gsum[gcur * HID + lane], acc);
    if (lane == 0) atomicAdd(&g_gcnt[gcur], ccnt);
}

// ---------------- K7: classifier ----------------
__global__ void final_kernel(const float* __restrict__ lin_w,
                             const float* __restrict__ lin_b,
                             float* __restrict__ out)
{
    int t = threadIdx.x;
    if (t >= N_GRAPHS * 2) return;
    int g = t >> 1, c = t & 1;
    float cnt = fmaxf(g_gcnt[g], 1.f);
    float s = 0.f;
    #pragma unroll
    for (int h = 0; h < HID; h++)
        s += g_gsum[g * HID + h] * lin_w[h * 2 + c];
    out[g * 2 + c] = s / cnt + lin_b[c];
}

// ---------------- launcher ----------------
extern "C" void kernel_launch(void* const* d_in, const int* in_sizes, int n_in,
                              void* d_out, int out_size) {
    const float* x    = (const float*)d_in[0];
    const int*   ei   = (const int*)  d_in[1];
    const float* ea   = (const float*)d_in[2];
    const int*   bat  = (const int*)  d_in[3];
    const float* w1   = (const float*)d_in[4];
    const float* b1   = (const float*)d_in[5];
    const float* w2   = (const float*)d_in[6];
    const float* b2   = (const float*)d_in[7];
    const float* root = (const float*)d_in[8];
    const float* cb   = (const float*)d_in[9];
    const float* lw   = (const float*)d_in[10];
    const float* lb   = (const float*)d_in[11];
    float* out = (float*)d_out;

    zero_kernel<<<1024, 256>>>();
    build_kernel<<<NBINS, 256>>>(w1, b1, w2, b2);
    hist_kernel<<<NEBLK, 256>>>(ea, ei, w1, b1);
    prefix_kernel<<<1, 1024>>>();
    scatter_kernel<<<NEBLK, 256>>>();
    edge2_kernel<<<NEBLK, 256>>>(x, ei, ea);
    node_kernel<<<(N_NODES + 63) / 64, 256>>>(x, bat, root, cb);
    final_kernel<<<1, 128>>>(lw, lb, out);
}

// round 6
// speedup vs baseline: 2.1087x; 1.4468x over previous
#include <cuda_runtime.h>

#define N_NODES 50000
#define N_EDGES 200000
#define IN_F 32
#define HID 32
#define N_GRAPHS 64
#define NBINS 65
#define EB 256                 // edges per block
#define NEBLK ((N_EDGES + EB - 1) / EB)

// ---------------- scratch (no allocs allowed) ----------------
__device__ float g_agg[N_NODES * HID];
__device__ float g_cnt[N_NODES];
__device__ float g_gsum[N_GRAPHS * HID];
__device__ float g_gcnt[N_GRAPHS];
__device__ float g_P[NBINS * 1024];
__device__ float g_Q[NBINS * 1024];
__device__ int   g_bhist[NBINS * NEBLK];
__device__ int   g_btot[NBINS];
__device__ int   g_bbase[NBINS];
__device__ int   g_sr[N_EDGES];      // s | (local_rank << 8)
__device__ int   g_perm[N_EDGES];    // e | (s << 18)

__device__ __forceinline__ float inf_f() { return __int_as_float(0x7f800000); }

__device__ __forceinline__ float key_of(float w, float b) {
    return (w != 0.f) ? (-b / w) : inf_f();
}

__device__ __forceinline__ void red_add_v4(float* p, float a, float b, float c, float d) {
    asm volatile("red.global.add.v4.f32 [%0], {%1,%2,%3,%4};"
                 :: "l"(p), "f"(a), "f"(b), "f"(c), "f"(d) : "memory");
}

// ---------------- K0: zero scratch ----------------
__global__ void zero_kernel() {
    int idx = blockIdx.x * blockDim.x + threadIdx.x;
    int stride = gridDim.x * blockDim.x;
    float4 z = make_float4(0.f, 0.f, 0.f, 0.f);
    float4* aggp = (float4*)g_agg;
    for (int i = idx; i < N_NODES * HID / 4; i += stride) aggp[i] = z;
    for (int i = idx; i < N_NODES; i += stride) g_cnt[i] = 0.f;
    if (idx < N_GRAPHS * HID) g_gsum[idx] = 0.f;
    if (idx < N_GRAPHS) g_gcnt[idx] = 0.f;
}

// ---------------- K1: build per-interval matrices P_s, Q_s ----------------
__global__ void __launch_bounds__(256) build_kernel(
    const float* __restrict__ w1, const float* __restrict__ b1,
    const float* __restrict__ w2, const float* __restrict__ b2)
{
    __shared__ float key[64], srt[64], wa[64], ba[64];
    const int t = threadIdx.x;
    const int s = blockIdx.x;

    if (t < 64) key[t] = key_of(w1[t], b1[t]);
    __syncthreads();
    if (t < 64) {
        float kt = key[t];
        int r = 0;
        #pragma unroll
        for (int k = 0; k < 64; k++) {
            float kk = key[k];
            r += (kk < kt) || (kk == kt && k < t);
        }
        srt[r] = kt;
    }
    __syncthreads();

    float lo = (s == 0)         ? 0.f : fminf(fmaxf(srt[s - 1], 0.f), 1.f);
    float hi = (s == NBINS - 1) ? 1.f : fminf(fmaxf(srt[s], 0.f), 1.f);
    float m  = 0.5f * (lo + hi);

    if (t < 64) {
        float w = w1[t], b = b1[t];
        bool act = (fmaf(m, w, b) > 0.f);
        wa[t] = act ? w : 0.f;
        ba[t] = act ? b : 0.f;
    }
    __syncthreads();

    for (int e = t; e < 1024; e += 256) {
        float p = 0.f, q = 0.f;
        #pragma unroll 8
        for (int j = 0; j < 64; j++) {
            float v = w2[j * 1024 + e];
            p = fmaf(wa[j], v, p);
            q = fmaf(ba[j], v, q);
        }
        g_P[s * 1024 + e] = p;
        g_Q[s * 1024 + e] = q + b2[e];
    }
}

// ---------------- K2: bin id + local rank + per-block hist + degrees ----------------
__global__ void __launch_bounds__(256) hist_kernel(
    const float* __restrict__ ea, const int* __restrict__ ei,
    const float* __restrict__ w1, const float* __restrict__ b1)
{
    __shared__ float key[64];
    __shared__ int lh[NBINS];
    const int t = threadIdx.x;
    if (t < 64) key[t] = key_of(w1[t], b1[t]);
    if (t < NBINS) lh[t] = 0;
    __syncthreads();

    int e = blockIdx.x * EB + t;
    if (e < N_EDGES) {
        float a = ea[e];
        int s = 0;
        #pragma unroll 16
        for (int k = 0; k < 64; k++) s += (key[k] < a) ? 1 : 0;
        int r = atomicAdd(&lh[s], 1);
        g_sr[e] = s | (r << 8);
        atomicAdd(&g_cnt[ei[N_EDGES + e]], 1.f);
    }
    __syncthreads();
    if (t < NBINS) g_bhist[t * NEBLK + blockIdx.x] = lh[t];
}

// ---------------- K3a: per-bin exclusive scan over 782 block counts ----------------
// grid = NBINS blocks of 256 threads; in-place on g_bhist; totals to g_btot.
__global__ void __launch_bounds__(256) bin_scan_kernel()
{
    __shared__ int wsum[8];
    __shared__ int total_sm;
    const int t = threadIdx.x;
    const int lane = t & 31, w = t >> 5;
    int* base = g_bhist + blockIdx.x * NEBLK;

    const int beg = t * 4;
    const int end = min(beg + 4, NEBLK);
    int v[4];
    int local = 0;
    #pragma unroll
    for (int i = 0; i < 4; i++) {
        int idx = beg + i;
        v[i] = (idx < NEBLK) ? base[idx] : 0;
        local += v[i];
    }

    // warp inclusive scan of per-thread sums
    int incl = local;
    #pragma unroll
    for (int d = 1; d < 32; d <<= 1) {
        int y = __shfl_up_sync(0xffffffffu, incl, d);
        if (lane >= d) incl += y;
    }
    if (lane == 31) wsum[w] = incl;
    __syncthreads();
    if (t == 0) {
        int acc = 0;
        #pragma unroll
        for (int i = 0; i < 8; i++) { int q = wsum[i]; wsum[i] = acc; acc += q; }
        total_sm = acc;
    }
    __syncthreads();

    int carry = incl - local + wsum[w];   // exclusive prefix for this thread
    #pragma unroll
    for (int i = 0; i < 4; i++) {
        int idx = beg + i;
        if (idx < NEBLK) { base[idx] = carry; carry += v[i]; }
    }
    if (t == 0) g_btot[blockIdx.x] = total_sm;
}

// ---------------- K3b: exclusive scan of 65 bin totals ----------------
__global__ void __launch_bounds__(128) base_scan_kernel()
{
    __shared__ int sv[128];
    int t = threadIdx.x;
    int v = (t < NBINS) ? g_btot[t] : 0;
    sv[t] = v;
    __syncthreads();
    #pragma unroll
    for (int d = 1; d < 128; d <<= 1) {
        int y = (t >= d) ? sv[t - d] : 0;
        __syncthreads();
        sv[t] += y;
        __syncthreads();
    }
    if (t < NBINS) g_bbase[t] = sv[t] - v;
}

// ---------------- K4: deterministic scatter (no atomics) ----------------
__global__ void __launch_bounds__(256) scatter_kernel()
{
    int e = blockIdx.x * EB + threadIdx.x;
    if (e < N_EDGES) {
        int sr = g_sr[e];
        int s = sr & 0xFF, r = sr >> 8;
        int pos = g_bbase[s] + g_bhist[s * NEBLK + blockIdx.x] + r;
        g_perm[pos] = e | (s << 18);
    }
}

// ---------------- K5: edge messages (fp32, table-based) ----------------
// msg_e = a_e * (x_src @ P_s) + (x_src @ Q_s)
__global__ void __launch_bounds__(256) edge2_kernel(
    const float* __restrict__ x, const int* __restrict__ ei,
    const float* __restrict__ ea)
{
    __shared__ float4 sP[256], sQ[256];   // 32x32 each, row i -> [i*8 .. i*8+7]
    const int t = threadIdx.x;
    const int base = blockIdx.x * EB;
    const int idx = base + t;
    const bool v = (idx < N_EDGES);

    const int endidx = min(base + EB - 1, N_EDGES - 1);
    int pk   = g_perm[v ? idx : endidx];
    const int e   = pk & 0x3FFFF;
    const int s_t = pk >> 18;
    const int s_lo = g_perm[base] >> 18;
    const int s_hi = g_perm[endidx] >> 18;

    const int src = ei[e];
    const int dst = ei[N_EDGES + e];
    const float a = ea[e];

    float xr[32];
    {
        const float4* xp = (const float4*)(x + src * IN_F);
        #pragma unroll
        for (int u = 0; u < 8; u++) {
            float4 f = xp[u];
            xr[4 * u] = f.x; xr[4 * u + 1] = f.y;
            xr[4 * u + 2] = f.z; xr[4 * u + 3] = f.w;
        }
    }

    for (int s = s_lo; s <= s_hi; s++) {
        bool mine = v && (s_t == s);
        if (!__syncthreads_or(mine ? 1 : 0)) continue;
        const float4* gp = (const float4*)(g_P + s * 1024);
        const float4* gq = (const float4*)(g_Q + s * 1024);
        sP[t] = gp[t]; sQ[t] = gq[t];
        __syncthreads();
        if (mine) {
            float* aggp = &g_agg[dst * HID];
            #pragma unroll
            for (int nc = 0; nc < 8; nc++) {
                float ux = 0.f, uy = 0.f, uz = 0.f, uw = 0.f;
                float qx = 0.f, qy = 0.f, qz = 0.f, qw = 0.f;
                #pragma unroll 8
                for (int i = 0; i < 32; i++) {
                    float xi = xr[i];
                    float4 pv = sP[i * 8 + nc];
                    float4 qv = sQ[i * 8 + nc];
                    ux = fmaf(xi, pv.x, ux); uy = fmaf(xi, pv.y, uy);
                    uz = fmaf(xi, pv.z, uz); uw = fmaf(xi, pv.w, uw);
                    qx = fmaf(xi, qv.x, qx); qy = fmaf(xi, qv.y, qy);
                    qz = fmaf(xi, qv.z, qz); qw = fmaf(xi, qv.w, qw);
                }
                red_add_v4(aggp + nc * 4,
                           fmaf(a, ux, qx), fmaf(a, uy, qy),
                           fmaf(a, uz, qz), fmaf(a, uw, qw));
            }
        }
        __syncthreads();
    }
}

// ---------------- K6: node update + graph pooling (run-length flush) ----------------
__global__ void __launch_bounds__(256) node_kernel(
    const float* __restrict__ x, const int* __restrict__ batch,
    const float* __restrict__ root, const float* __restrict__ conv_bias)
{
    int wrp = threadIdx.x >> 5, lane = threadIdx.x & 31;
    int n0 = (blockIdx.x * 8 + wrp) * 8;
    if (n0 >= N_NODES) return;

    float rt[32];
    #pragma unroll
    for (int i = 0; i < IN_F; i++) rt[i] = root[i * HID + lane];
    const float cb = conv_bias[lane];

    float acc = 0.f, ccnt = 0.f;
    int gcur = batch[n0];
    #pragma unroll
    for (int k = 0; k < 8; k++) {
        int n = n0 + k;
        if (n >= N_NODES) break;
        int g = batch[n];
        if (g != gcur) {
            atomicAdd(&g_gsum[gcur * HID + lane], acc);
            if (lane == 0) atomicAdd(&g_gcnt[gcur], ccnt);
            acc = 0.f; ccnt = 0.f; gcur = g;
        }
        float vv = g_agg[n * HID + lane] / fmaxf(g_cnt[n], 1.f);
        float xv = x[n * IN_F + lane];
        float ss = 0.f;
        #pragma unroll
        for (int i = 0; i < IN_F; i++)
            ss = fmaf(__shfl_sync(0xffffffffu, xv, i), rt[i], ss);
        acc += fmaxf(vv + ss + cb, 0.f);
        ccnt += 1.f;
    }
    atomicAdd(&g_gsum[gcur * HID + lane], acc);
    if (lane == 0) atomicAdd(&g_gcnt[gcur], ccnt);
}

// ---------------- K7: classifier ----------------
__global__ void final_kernel(const float* __restrict__ lin_w,
                             const float* __restrict__ lin_b,
                             float* __restrict__ out)
{
    int t = threadIdx.x;
    if (t >= N_GRAPHS * 2) return;
    int g = t >> 1, c = t & 1;
    float cnt = fmaxf(g_gcnt[g], 1.f);
    float s = 0.f;
    #pragma unroll
    for (int h = 0; h < HID; h++)
        s += g_gsum[g * HID + h] * lin_w[h * 2 + c];
    out[g * 2 + c] = s / cnt + lin_b[c];
}

// ---------------- launcher ----------------
extern "C" void kernel_launch(void* const* d_in, const int* in_sizes, int n_in,
                              void* d_out, int out_size) {
    const float* x    = (const float*)d_in[0];
    const int*   ei   = (const int*)  d_in[1];
    const float* ea   = (const float*)d_in[2];
    const int*   bat  = (const int*)  d_in[3];
    const float* w1   = (const float*)d_in[4];
    const float* b1   = (const float*)d_in[5];
    const float* w2   = (const float*)d_in[6];
    const float* b2   = (const float*)d_in[7];
    const float* root = (const float*)d_in[8];
    const float* cb   = (const float*)d_in[9];
    const float* lw   = (const float*)d_in[10];
    const float* lb   = (const float*)d_in[11];
    float* out = (float*)d_out;

    zero_kernel<<<1024, 256>>>();
    build_kernel<<<NBINS, 256>>>(w1, b1, w2, b2);
    hist_kernel<<<NEBLK, 256>>>(ea, ei, w1, b1);
    bin_scan_kernel<<<NBINS, 256>>>();
    base_scan_kernel<<<1, 128>>>();
    scatter_kernel<<<NEBLK, 256>>>();
    edge2_kernel<<<NEBLK, 256>>>(x, ei, ea);
    node_kernel<<<(N_NODES + 63) / 64, 256>>>(x, bat, root, cb);
    final_kernel<<<1, 128>>>(lw, lb, out);
}

// round 7
// speedup vs baseline: 3.0109x; 1.4278x over previous
#include <cuda_runtime.h>

#define N_NODES 50000
#define N_EDGES 200000
#define IN_F 32
#define HID 32
#define N_GRAPHS 64
#define NBINS 65
#define EB 256                 // edges per block
#define NEBLK ((N_EDGES + EB - 1) / EB)

// ---------------- scratch (no allocs allowed) ----------------
__device__ float g_agg[N_NODES * HID];
__device__ float g_cnt[N_NODES];
__device__ float g_gsum[N_GRAPHS * HID];
__device__ float g_gcnt[N_GRAPHS];
__device__ float g_P[NBINS * 1024];
__device__ float g_Q[NBINS * 1024];
__device__ int   g_bhist[NBINS * NEBLK];
__device__ int   g_btot[NBINS];
__device__ int   g_sr[N_EDGES];      // s | (local_rank << 8)
__device__ int   g_perm[N_EDGES];    // e | (s << 18)

__device__ __forceinline__ float inf_f() { return __int_as_float(0x7f800000); }

__device__ __forceinline__ float key_of(float w, float b) {
    return (w != 0.f) ? (-b / w) : inf_f();
}

__device__ __forceinline__ unsigned f2tf32(float f) {
    unsigned r;
    asm("cvt.rna.tf32.f32 %0, %1;" : "=r"(r) : "f"(f));
    return r;
}

__device__ __forceinline__ void red_add_v2(float* p, float a, float b) {
    asm volatile("red.global.add.v2.f32 [%0], {%1,%2};"
                 :: "l"(p), "f"(a), "f"(b) : "memory");
}

// D = A*B + D
#define MMA_ACC(C, a0, a1, a2, a3, B0, B1)                                      \
    asm volatile("mma.sync.aligned.m16n8k8.row.col.f32.tf32.tf32.f32 "          \
                 "{%0,%1,%2,%3}, {%4,%5,%6,%7}, {%8,%9}, {%0,%1,%2,%3};"        \
                 : "+f"((C)[0]), "+f"((C)[1]), "+f"((C)[2]), "+f"((C)[3])       \
                 : "r"(a0), "r"(a1), "r"(a2), "r"(a3), "r"(B0), "r"(B1))

// D = A*B (zero C)
#define MMA_SET(C, a0, a1, a2, a3, B0, B1)                                      \
    asm volatile("mma.sync.aligned.m16n8k8.row.col.f32.tf32.tf32.f32 "          \
                 "{%0,%1,%2,%3}, {%4,%5,%6,%7}, {%8,%9}, {%10,%11,%12,%13};"    \
                 : "=f"((C)[0]), "=f"((C)[1]), "=f"((C)[2]), "=f"((C)[3])       \
                 : "r"(a0), "r"(a1), "r"(a2), "r"(a3), "r"(B0), "r"(B1),        \
                   "f"(0.f), "f"(0.f), "f"(0.f), "f"(0.f))

// ---------------- K0: zero scratch ----------------
__global__ void zero_kernel() {
    int idx = blockIdx.x * blockDim.x + threadIdx.x;
    int stride = gridDim.x * blockDim.x;
    float4 z = make_float4(0.f, 0.f, 0.f, 0.f);
    float4* aggp = (float4*)g_agg;
    for (int i = idx; i < N_NODES * HID / 4; i += stride) aggp[i] = z;
    for (int i = idx; i < N_NODES; i += stride) g_cnt[i] = 0.f;
    if (idx < N_GRAPHS * HID) g_gsum[idx] = 0.f;
    if (idx < N_GRAPHS) g_gcnt[idx] = 0.f;
}

// ---------------- K1: build per-interval matrices P_s, Q_s ----------------
__global__ void __launch_bounds__(256) build_kernel(
    const float* __restrict__ w1, const float* __restrict__ b1,
    const float* __restrict__ w2, const float* __restrict__ b2)
{
    __shared__ float key[64], srt[64], wa[64], ba[64];
    const int t = threadIdx.x;
    const int s = blockIdx.x;

    if (t < 64) key[t] = key_of(w1[t], b1[t]);
    __syncthreads();
    if (t < 64) {
        float kt = key[t];
        int r = 0;
        #pragma unroll
        for (int k = 0; k < 64; k++) {
            float kk = key[k];
            r += (kk < kt) || (kk == kt && k < t);
        }
        srt[r] = kt;
    }
    __syncthreads();

    float lo = (s == 0)         ? 0.f : fminf(fmaxf(srt[s - 1], 0.f), 1.f);
    float hi = (s == NBINS - 1) ? 1.f : fminf(fmaxf(srt[s], 0.f), 1.f);
    float m  = 0.5f * (lo + hi);

    if (t < 64) {
        float w = w1[t], b = b1[t];
        bool act = (fmaf(m, w, b) > 0.f);
        wa[t] = act ? w : 0.f;
        ba[t] = act ? b : 0.f;
    }
    __syncthreads();

    for (int e = t; e < 1024; e += 256) {
        float p = 0.f, q = 0.f;
        #pragma unroll 8
        for (int j = 0; j < 64; j++) {
            float v = w2[j * 1024 + e];
            p = fmaf(wa[j], v, p);
            q = fmaf(ba[j], v, q);
        }
        g_P[s * 1024 + e] = p;
        g_Q[s * 1024 + e] = q + b2[e];
    }
}

// ---------------- K2: bin id + local rank + per-block hist + degrees ----------------
__global__ void __launch_bounds__(256) hist_kernel(
    const float* __restrict__ ea, const int* __restrict__ ei,
    const float* __restrict__ w1, const float* __restrict__ b1)
{
    __shared__ float key[64];
    __shared__ int lh[NBINS];
    const int t = threadIdx.x;
    if (t < 64) key[t] = key_of(w1[t], b1[t]);
    if (t < NBINS) lh[t] = 0;
    __syncthreads();

    int e = blockIdx.x * EB + t;
    if (e < N_EDGES) {
        float a = ea[e];
        int s = 0;
        #pragma unroll 16
        for (int k = 0; k < 64; k++) s += (key[k] < a) ? 1 : 0;
        int r = atomicAdd(&lh[s], 1);
        g_sr[e] = s | (r << 8);
        atomicAdd(&g_cnt[ei[N_EDGES + e]], 1.f);
    }
    __syncthreads();
    if (t < NBINS) g_bhist[t * NEBLK + blockIdx.x] = lh[t];
}

// ---------------- K3: per-bin exclusive scan over 782 block counts ----------------
__global__ void __launch_bounds__(256) bin_scan_kernel()
{
    __shared__ int wsum[8];
    __shared__ int total_sm;
    const int t = threadIdx.x;
    const int lane = t & 31, w = t >> 5;
    int* base = g_bhist + blockIdx.x * NEBLK;

    const int beg = t * 4;
    int v[4];
    int local = 0;
    #pragma unroll
    for (int i = 0; i < 4; i++) {
        int idx = beg + i;
        v[i] = (idx < NEBLK) ? base[idx] : 0;
        local += v[i];
    }

    int incl = local;
    #pragma unroll
    for (int d = 1; d < 32; d <<= 1) {
        int y = __shfl_up_sync(0xffffffffu, incl, d);
        if (lane >= d) incl += y;
    }
    if (lane == 31) wsum[w] = incl;
    __syncthreads();
    if (t == 0) {
        int acc = 0;
        #pragma unroll
        for (int i = 0; i < 8; i++) { int q = wsum[i]; wsum[i] = acc; acc += q; }
        total_sm = acc;
    }
    __syncthreads();

    int carry = incl - local + wsum[w];
    #pragma unroll
    for (int i = 0; i < 4; i++) {
        int idx = beg + i;
        if (idx < NEBLK) { base[idx] = carry; carry += v[i]; }
    }
    if (t == 0) g_btot[blockIdx.x] = total_sm;
}

// ---------------- K4: deterministic scatter (base scan fused, no atomics) ----
__global__ void __launch_bounds__(256) scatter_kernel()
{
    __shared__ int sbase[NBINS];
    const int t = threadIdx.x;
    if (t == 0) {
        int acc = 0;
        #pragma unroll
        for (int i = 0; i < NBINS; i++) { sbase[i] = acc; acc += g_btot[i]; }
    }
    __syncthreads();
    int e = blockIdx.x * EB + t;
    if (e < N_EDGES) {
        int sr = g_sr[e];
        int s = sr & 0xFF, r = sr >> 8;
        int pos = sbase[s] + g_bhist[s * NEBLK + blockIdx.x] + r;
        g_perm[pos] = e | (s << 18);
    }
}

// ---------------- K5: edge messages via tf32 MMA ----------------
// msg_e = (a_e * x_src) @ P_s + x_src @ Q_s  -> one K=64 GEMM [a*x | x] @ [P;Q]
// smem B layout: combined [64k x 32n], rows paired (k, k+4):
//   k = kq*8 + c0p + 4*hi  ->  sB[(kq*4+c0p)*66 + n*2 + hi]   (stride 66 skew)
// Consumer (lane r0, c0): uint2 at (kq*4+c0)*66 + (nb*8+r0)*2 = {B[k], B[k+4]}.
__global__ void __launch_bounds__(256) edge2_kernel(
    const float* __restrict__ x, const int* __restrict__ ei,
    const float* __restrict__ ea)
{
    __shared__ unsigned sB[32 * 66];
    const int t = threadIdx.x;
    const int lane = t & 31, wrp = t >> 5;
    const int r0 = lane >> 2, c0 = lane & 3;
    const int base = blockIdx.x * EB;
    const int endidx = min(base + EB - 1, N_EDGES - 1);
    const int s_lo = g_perm[base] >> 18;
    const int s_hi = g_perm[endidx] >> 18;

    int dstv[4];
    int sse[4];
    unsigned af[4][8], xf[4][8];   // tf32 frags: a*x (k 0..31) and x (k 32..63)

    #pragma unroll
    for (int t4 = 0; t4 < 4; t4++) {
        int ridx = base + wrp * 32 + r0 + t4 * 8;
        bool v = (ridx < N_EDGES);
        int pk = g_perm[v ? ridx : endidx];
        int e = pk & 0x3FFFF;
        sse[t4] = v ? (pk >> 18) : -1;
        int src = ei[e];
        dstv[t4] = ei[N_EDGES + e];
        float a = ea[e];
        const float* xr = x + src * IN_F;
        #pragma unroll
        for (int q = 0; q < 8; q++) {
            float xv = xr[c0 + 4 * q];
            xf[t4][q] = f2tf32(xv);
            af[t4][q] = f2tf32(a * xv);
        }
    }

    for (int s = s_lo; s <= s_hi; s++) {
        bool mine = (sse[0] == s) | (sse[1] == s) | (sse[2] == s) | (sse[3] == s);
        if (!__syncthreads_or(mine ? 1 : 0)) continue;

        // stage [P_s; Q_s] as tf32
        #pragma unroll
        for (int u = 0; u < 8; u++) {
            int idx = u * 256 + t;          // 0..2047
            int k = idx >> 5, n = idx & 31;
            float v = (k < 32) ? g_P[s * 1024 + k * 32 + n]
                               : g_Q[s * 1024 + (k - 32) * 32 + n];
            int kq = k >> 3, kl = k & 7;
            int c0p = kl & 3, hi = kl >> 2;
            sB[(kq * 4 + c0p) * 66 + n * 2 + hi] = f2tf32(v);
        }
        __syncthreads();

        float acc[2][4][4];
        #pragma unroll
        for (int nb = 0; nb < 4; nb++) {
            #pragma unroll
            for (int kq = 0; kq < 8; kq++) {
                uint2 b = *(const uint2*)&sB[(kq * 4 + c0) * 66 + (nb * 8 + r0) * 2];
                const int q0 = (2 * kq) & 7;
                const unsigned* F0 = (kq < 4) ? af[0] : xf[0];
                const unsigned* F1 = (kq < 4) ? af[1] : xf[1];
                const unsigned* F2 = (kq < 4) ? af[2] : xf[2];
                const unsigned* F3 = (kq < 4) ? af[3] : xf[3];
                if (kq == 0) {
                    MMA_SET(acc[0][nb], F0[q0], F1[q0], F0[q0 + 1], F1[q0 + 1], b.x, b.y);
                    MMA_SET(acc[1][nb], F2[q0], F3[q0], F2[q0 + 1], F3[q0 + 1], b.x, b.y);
                } else {
                    MMA_ACC(acc[0][nb], F0[q0], F1[q0], F0[q0 + 1], F1[q0 + 1], b.x, b.y);
                    MMA_ACC(acc[1][nb], F2[q0], F3[q0], F2[q0 + 1], F3[q0 + 1], b.x, b.y);
                }
            }
        }

        // predicated scatter (rows of this bin only)
        #pragma unroll
        for (int mt = 0; mt < 2; mt++) {
            int te = mt * 2, to = mt * 2 + 1;
            #pragma unroll
            for (int nb = 0; nb < 4; nb++) {
                int n = nb * 8 + 2 * c0;
                if (sse[te] == s)
                    red_add_v2(&g_agg[dstv[te] * HID + n], acc[mt][nb][0], acc[mt][nb][1]);
                if (sse[to] == s)
                    red_add_v2(&g_agg[dstv[to] * HID + n], acc[mt][nb][2], acc[mt][nb][3]);
            }
        }
        __syncthreads();
    }
}

// ---------------- K6: node update + graph pooling (run-length flush) ----------------
__global__ void __launch_bounds__(256) node_kernel(
    const float* __restrict__ x, const int* __restrict__ batch,
    const float* __restrict__ root, const float* __restrict__ conv_bias)
{
    int wrp = threadIdx.x >> 5, lane = threadIdx.x & 31;
    int n0 = (blockIdx.x * 8 + wrp) * 8;
    if (n0 >= N_NODES) return;

    float rt[32];
    #pragma unroll
    for (int i = 0; i < IN_F; i++) rt[i] = root[i * HID + lane];
    const float cb = conv_bias[lane];

    float acc = 0.f, ccnt = 0.f;
    int gcur = batch[n0];
    #pragma unroll
    for (int k = 0; k < 8; k++) {
        int n = n0 + k;
        if (n >= N_NODES) break;
        int g = batch[n];
        if (g != gcur) {
            atomicAdd(&g_gsum[gcur * HID + lane], acc);
            if (lane == 0) atomicAdd(&g_gcnt[gcur], ccnt);
            acc = 0.f; ccnt = 0.f; gcur = g;
        }
        float vv = g_agg[n * HID + lane] / fmaxf(g_cnt[n], 1.f);
        float xv = x[n * IN_F + lane];
        float ss = 0.f;
        #pragma unroll
        for (int i = 0; i < IN_F; i++)
            ss = fmaf(__shfl_sync(0xffffffffu, xv, i), rt[i], ss);
        acc += fmaxf(vv + ss + cb, 0.f);
        ccnt += 1.f;
    }
    atomicAdd(&g_gsum[gcur * HID + lane], acc);
    if (lane == 0) atomicAdd(&g_gcnt[gcur], ccnt);
}

// ---------------- K7: classifier ----------------
__global__ void final_kernel(const float* __restrict__ lin_w,
                             const float* __restrict__ lin_b,
                             float* __restrict__ out)
{
    int t = threadIdx.x;
    if (t >= N_GRAPHS * 2) return;
    int g = t >> 1, c = t & 1;
    float cnt = fmaxf(g_gcnt[g], 1.f);
    float s = 0.f;
    #pragma unroll
    for (int h = 0; h < HID; h++)
        s += g_gsum[g * HID + h] * lin_w[h * 2 + c];
    out[g * 2 + c] = s / cnt + lin_b[c];
}

// ---------------- launcher ----------------
extern "C" void kernel_launch(void* const* d_in, const int* in_sizes, int n_in,
                              void* d_out, int out_size) {
    const float* x    = (const float*)d_in[0];
    const int*   ei   = (const int*)  d_in[1];
    const float* ea   = (const float*)d_in[2];
    const int*   bat  = (const int*)  d_in[3];
    const float* w1   = (const float*)d_in[4];
    const float* b1   = (const float*)d_in[5];
    const float* w2   = (const float*)d_in[6];
    const float* b2   = (const float*)d_in[7];
    const float* root = (const float*)d_in[8];
    const float* cb   = (const float*)d_in[9];
    const float* lw   = (const float*)d_in[10];
    const float* lb   = (const float*)d_in[11];
    float* out = (float*)d_out;

    zero_kernel<<<1024, 256>>>();
    build_kernel<<<NBINS, 256>>>(w1, b1, w2, b2);
    hist_kernel<<<NEBLK, 256>>>(ea, ei, w1, b1);
    bin_scan_kernel<<<NBINS, 256>>>();
    scatter_kernel<<<NEBLK, 256>>>();
    edge2_kernel<<<NEBLK, 256>>>(x, ei, ea);
    node_kernel<<<(N_NODES + 63) / 64, 256>>>(x, bat, root, cb);
    final_kernel<<<1, 128>>>(lw, lb, out);
}

// round 8
// speedup vs baseline: 3.1080x; 1.0322x over previous
#include <cuda_runtime.h>

#define N_NODES 50000
#define N_EDGES 200000
#define IN_F 32
#define HID 32
#define N_GRAPHS 64
#define NBINS 65
#define EB 256                 // edges per block
#define NEBLK ((N_EDGES + EB - 1) / EB)

// ---------------- scratch (no allocs allowed) ----------------
__device__ float g_agg[N_NODES * HID];
__device__ float g_cnt[N_NODES];
__device__ float g_P[NBINS * 1024];
__device__ float g_Q[NBINS * 1024];
__device__ int   g_bhist[NBINS * NEBLK];
__device__ int   g_btot[NBINS];
__device__ int   g_sr[N_EDGES];      // s | (local_rank << 8)
__device__ int   g_perm[N_EDGES];    // e | (s << 18)
__device__ int   g_gs[N_GRAPHS];     // graph start node
__device__ int   g_ge[N_GRAPHS];     // graph end node (exclusive)

__device__ __forceinline__ float inf_f() { return __int_as_float(0x7f800000); }

__device__ __forceinline__ float key_of(float w, float b) {
    return (w != 0.f) ? (-b / w) : inf_f();
}

__device__ __forceinline__ unsigned f2tf32(float f) {
    unsigned r;
    asm("cvt.rna.tf32.f32 %0, %1;" : "=r"(r) : "f"(f));
    return r;
}

__device__ __forceinline__ void red_add_v2(float* p, float a, float b) {
    asm volatile("red.global.add.v2.f32 [%0], {%1,%2};"
                 :: "l"(p), "f"(a), "f"(b) : "memory");
}

#define MMA_ACC(C, a0, a1, a2, a3, B0, B1)                                      \
    asm volatile("mma.sync.aligned.m16n8k8.row.col.f32.tf32.tf32.f32 "          \
                 "{%0,%1,%2,%3}, {%4,%5,%6,%7}, {%8,%9}, {%0,%1,%2,%3};"        \
                 : "+f"((C)[0]), "+f"((C)[1]), "+f"((C)[2]), "+f"((C)[3])       \
                 : "r"(a0), "r"(a1), "r"(a2), "r"(a3), "r"(B0), "r"(B1))

#define MMA_SET(C, a0, a1, a2, a3, B0, B1)                                      \
    asm volatile("mma.sync.aligned.m16n8k8.row.col.f32.tf32.tf32.f32 "          \
                 "{%0,%1,%2,%3}, {%4,%5,%6,%7}, {%8,%9}, {%10,%11,%12,%13};"    \
                 : "=f"((C)[0]), "=f"((C)[1]), "=f"((C)[2]), "=f"((C)[3])       \
                 : "r"(a0), "r"(a1), "r"(a2), "r"(a3), "r"(B0), "r"(B1),        \
                   "f"(0.f), "f"(0.f), "f"(0.f), "f"(0.f))

// ---------------- K1: build per-interval matrices P_s, Q_s ----------------
__global__ void __launch_bounds__(256) build_kernel(
    const float* __restrict__ w1, const float* __restrict__ b1,
    const float* __restrict__ w2, const float* __restrict__ b2)
{
    __shared__ float key[64], srt[64], wa[64], ba[64];
    const int t = threadIdx.x;
    const int s = blockIdx.x;

    if (s == 0 && t < N_GRAPHS) { g_gs[t] = 0; g_ge[t] = 0; }

    if (t < 64) key[t] = key_of(w1[t], b1[t]);
    __syncthreads();
    if (t < 64) {
        float kt = key[t];
        int r = 0;
        #pragma unroll
        for (int k = 0; k < 64; k++) {
            float kk = key[k];
            r += (kk < kt) || (kk == kt && k < t);
        }
        srt[r] = kt;
    }
    __syncthreads();

    float lo = (s == 0)         ? 0.f : fminf(fmaxf(srt[s - 1], 0.f), 1.f);
    float hi = (s == NBINS - 1) ? 1.f : fminf(fmaxf(srt[s], 0.f), 1.f);
    float m  = 0.5f * (lo + hi);

    if (t < 64) {
        float w = w1[t], b = b1[t];
        bool act = (fmaf(m, w, b) > 0.f);
        wa[t] = act ? w : 0.f;
        ba[t] = act ? b : 0.f;
    }
    __syncthreads();

    for (int e = t; e < 1024; e += 256) {
        float p = 0.f, q = 0.f;
        #pragma unroll 8
        for (int j = 0; j < 64; j++) {
            float v = w2[j * 1024 + e];
            p = fmaf(wa[j], v, p);
            q = fmaf(ba[j], v, q);
        }
        g_P[s * 1024 + e] = p;
        g_Q[s * 1024 + e] = q + b2[e];
    }
}

// ---------------- K2: bin id + rank + block hist + zeroing + graph bounds ----
__global__ void __launch_bounds__(256) hist_kernel(
    const float* __restrict__ ea, const int* __restrict__ batch,
    const float* __restrict__ w1, const float* __restrict__ b1)
{
    __shared__ float key[64];
    __shared__ int lh[NBINS];
    const int t = threadIdx.x;
    const int gid = blockIdx.x * EB + t;
    if (t < 64) key[t] = key_of(w1[t], b1[t]);
    if (t < NBINS) lh[t] = 0;

    // zero g_agg / g_cnt (grid-stride; completes before scatter/edge2/node)
    {
        float4 z = make_float4(0.f, 0.f, 0.f, 0.f);
        float4* aggp = (float4*)g_agg;
        for (int i = gid; i < N_NODES * HID / 4; i += NEBLK * EB) aggp[i] = z;
        if (gid < N_NODES) g_cnt[gid] = 0.f;
    }

    // graph boundary detection on sorted batch
    if (gid < N_NODES) {
        int b = batch[gid];
        int bp = (gid > 0) ? batch[gid - 1] : -1;
        if (b != bp) {
            g_gs[b] = gid;
            if (gid > 0) g_ge[bp] = gid;
        }
        if (gid == N_NODES - 1) g_ge[b] = N_NODES;
    }
    __syncthreads();

    if (gid < N_EDGES) {
        float a = ea[gid];
        int s = 0;
        #pragma unroll 16
        for (int k = 0; k < 64; k++) s += (key[k] < a) ? 1 : 0;
        int r = atomicAdd(&lh[s], 1);
        g_sr[gid] = s | (r << 8);
    }
    __syncthreads();
    if (t < NBINS) g_bhist[t * NEBLK + blockIdx.x] = lh[t];
}

// ---------------- K3: per-bin exclusive scan + out init ----------------
__global__ void __launch_bounds__(256) bin_scan_kernel(
    float* __restrict__ out, const float* __restrict__ lin_b)
{
    __shared__ int wsum[8];
    __shared__ int total_sm;
    const int t = threadIdx.x;
    const int lane = t & 31, w = t >> 5;
    int* base = g_bhist + blockIdx.x * NEBLK;

    if (blockIdx.x == 0 && t < N_GRAPHS * 2) out[t] = lin_b[t & 1];

    const int beg = t * 4;
    int v[4];
    int local = 0;
    #pragma unroll
    for (int i = 0; i < 4; i++) {
        int idx = beg + i;
        v[i] = (idx < NEBLK) ? base[idx] : 0;
        local += v[i];
    }

    int incl = local;
    #pragma unroll
    for (int d = 1; d < 32; d <<= 1) {
        int y = __shfl_up_sync(0xffffffffu, incl, d);
        if (lane >= d) incl += y;
    }
    if (lane == 31) wsum[w] = incl;
    __syncthreads();
    if (t == 0) {
        int acc = 0;
        #pragma unroll
        for (int i = 0; i < 8; i++) { int q = wsum[i]; wsum[i] = acc; acc += q; }
        total_sm = acc;
    }
    __syncthreads();

    int carry = incl - local + wsum[w];
    #pragma unroll
    for (int i = 0; i < 4; i++) {
        int idx = beg + i;
        if (idx < NEBLK) { base[idx] = carry; carry += v[i]; }
    }
    if (t == 0) g_btot[blockIdx.x] = total_sm;
}

// ---------------- K4: deterministic scatter + degree counts ----------------
__global__ void __launch_bounds__(256) scatter_kernel(const int* __restrict__ ei)
{
    __shared__ int sbase[NBINS];
    const int t = threadIdx.x;
    if (t == 0) {
        int acc = 0;
        #pragma unroll
        for (int i = 0; i < NBINS; i++) { sbase[i] = acc; acc += g_btot[i]; }
    }
    __syncthreads();
    int e = blockIdx.x * EB + t;
    if (e < N_EDGES) {
        int sr = g_sr[e];
        int s = sr & 0xFF, r = sr >> 8;
        int pos = sbase[s] + g_bhist[s * NEBLK + blockIdx.x] + r;
        g_perm[pos] = e | (s << 18);
        atomicAdd(&g_cnt[ei[N_EDGES + e]], 1.f);
    }
}

// ---------------- K5: edge messages via tf32 MMA ----------------
// msg_e = (a_e * x_src) @ P_s + x_src @ Q_s  -> one K=64 GEMM [a*x | x] @ [P;Q]
__global__ void __launch_bounds__(256) edge2_kernel(
    const float* __restrict__ x, const int* __restrict__ ei,
    const float* __restrict__ ea)
{
    __shared__ unsigned sB[32 * 66];
    const int t = threadIdx.x;
    const int lane = t & 31, wrp = t >> 5;
    const int r0 = lane >> 2, c0 = lane & 3;
    const int base = blockIdx.x * EB;
    const int endidx = min(base + EB - 1, N_EDGES - 1);
    const int s_lo = g_perm[base] >> 18;
    const int s_hi = g_perm[endidx] >> 18;

    int dstv[4];
    int sse[4];
    unsigned af[4][8], xf[4][8];

    #pragma unroll
    for (int t4 = 0; t4 < 4; t4++) {
        int ridx = base + wrp * 32 + r0 + t4 * 8;
        bool v = (ridx < N_EDGES);
        int pk = g_perm[v ? ridx : endidx];
        int e = pk & 0x3FFFF;
        sse[t4] = v ? (pk >> 18) : -1;
        int src = ei[e];
        dstv[t4] = ei[N_EDGES + e];
        float a = ea[e];
        const float* xr = x + src * IN_F;
        #pragma unroll
        for (int q = 0; q < 8; q++) {
            float xv = xr[c0 + 4 * q];
            xf[t4][q] = f2tf32(xv);
            af[t4][q] = f2tf32(a * xv);
        }
    }

    for (int s = s_lo; s <= s_hi; s++) {
        bool mine = (sse[0] == s) | (sse[1] == s) | (sse[2] == s) | (sse[3] == s);
        if (!__syncthreads_or(mine ? 1 : 0)) continue;

        #pragma unroll
        for (int u = 0; u < 8; u++) {
            int idx = u * 256 + t;
            int k = idx >> 5, n = idx & 31;
            float v = (k < 32) ? g_P[s * 1024 + k * 32 + n]
                               : g_Q[s * 1024 + (k - 32) * 32 + n];
            int kq = k >> 3, kl = k & 7;
            int c0p = kl & 3, hi = kl >> 2;
            sB[(kq * 4 + c0p) * 66 + n * 2 + hi] = f2tf32(v);
        }
        __syncthreads();

        float acc[2][4][4];
        #pragma unroll
        for (int nb = 0; nb < 4; nb++) {
            #pragma unroll
            for (int kq = 0; kq < 8; kq++) {
                uint2 b = *(const uint2*)&sB[(kq * 4 + c0) * 66 + (nb * 8 + r0) * 2];
                const int q0 = (2 * kq) & 7;
                const unsigned* F0 = (kq < 4) ? af[0] : xf[0];
                const unsigned* F1 = (kq < 4) ? af[1] : xf[1];
                const unsigned* F2 = (kq < 4) ? af[2] : xf[2];
                const unsigned* F3 = (kq < 4) ? af[3] : xf[3];
                if (kq == 0) {
                    MMA_SET(acc[0][nb], F0[q0], F1[q0], F0[q0 + 1], F1[q0 + 1], b.x, b.y);
                    MMA_SET(acc[1][nb], F2[q0], F3[q0], F2[q0 + 1], F3[q0 + 1], b.x, b.y);
                } else {
                    MMA_ACC(acc[0][nb], F0[q0], F1[q0], F0[q0 + 1], F1[q0 + 1], b.x, b.y);
                    MMA_ACC(acc[1][nb], F2[q0], F3[q0], F2[q0 + 1], F3[q0 + 1], b.x, b.y);
                }
            }
        }

        #pragma unroll
        for (int mt = 0; mt < 2; mt++) {
            int te = mt * 2, to = mt * 2 + 1;
            #pragma unroll
            for (int nb = 0; nb < 4; nb++) {
                int n = nb * 8 + 2 * c0;
                if (sse[te] == s)
                    red_add_v2(&g_agg[dstv[te] * HID + n], acc[mt][nb][0], acc[mt][nb][1]);
                if (sse[to] == s)
                    red_add_v2(&g_agg[dstv[to] * HID + n], acc[mt][nb][2], acc[mt][nb][3]);
            }
        }
        __syncthreads();
    }
}

// ---------------- K6: node update + pooling + classifier (fused) ------------
__global__ void __launch_bounds__(256) node_kernel(
    const float* __restrict__ x, const int* __restrict__ batch,
    const float* __restrict__ root, const float* __restrict__ conv_bias,
    const float* __restrict__ lin_w, float* __restrict__ out)
{
    int wrp = threadIdx.x >> 5, lane = threadIdx.x & 31;
    int n0 = (blockIdx.x * 8 + wrp) * 8;
    if (n0 >= N_NODES) return;

    float rt[32];
    #pragma unroll
    for (int i = 0; i < IN_F; i++) rt[i] = root[i * HID + lane];
    const float cb = conv_bias[lane];
    const float lw0 = lin_w[lane * 2 + 0];
    const float lw1 = lin_w[lane * 2 + 1];

    float acc = 0.f;                  // per-lane node-vector sum for current graph
    int gcur = batch[n0];
    #pragma unroll
    for (int k = 0; k < 8; k++) {
        int n = n0 + k;
        if (n >= N_NODES) break;
        int g = batch[n];
        if (g != gcur) {
            // flush: project through lin_w, scale by 1/cnt, atomic to out
            float s0 = acc * lw0, s1 = acc * lw1;
            #pragma unroll
            for (int d = 16; d > 0; d >>= 1) {
                s0 += __shfl_xor_sync(0xffffffffu, s0, d);
                s1 += __shfl_xor_sync(0xffffffffu, s1, d);
            }
            if (lane == 0) {
                float inv = 1.f / fmaxf((float)(g_ge[gcur] - g_gs[gcur]), 1.f);
                atomicAdd(&out[gcur * 2 + 0], s0 * inv);
                atomicAdd(&out[gcur * 2 + 1], s1 * inv);
            }
            acc = 0.f; gcur = g;
        }
        float vv = g_agg[n * HID + lane] / fmaxf(g_cnt[n], 1.f);
        float xv = x[n * IN_F + lane];
        float ss = 0.f;
        #pragma unroll
        for (int i = 0; i < IN_F; i++)
            ss = fmaf(__shfl_sync(0xffffffffu, xv, i), rt[i], ss);
        acc += fmaxf(vv + ss + cb, 0.f);
    }
    {
        float s0 = acc * lw0, s1 = acc * lw1;
        #pragma unroll
        for (int d = 16; d > 0; d >>= 1) {
            s0 += __shfl_xor_sync(0xffffffffu, s0, d);
            s1 += __shfl_xor_sync(0xffffffffu, s1, d);
        }
        if (lane == 0) {
            float inv = 1.f / fmaxf((float)(g_ge[gcur] - g_gs[gcur]), 1.f);
            atomicAdd(&out[gcur * 2 + 0], s0 * inv);
            atomicAdd(&out[gcur * 2 + 1], s1 * inv);
        }
    }
}

// ---------------- launcher ----------------
extern "C" void kernel_launch(void* const* d_in, const int* in_sizes, int n_in,
                              void* d_out, int out_size) {
    const float* x    = (const float*)d_in[0];
    const int*   ei   = (const int*)  d_in[1];
    const float* ea   = (const float*)d_in[2];
    const int*   bat  = (const int*)  d_in[3];
    const float* w1   = (const float*)d_in[4];
    const float* b1   = (const float*)d_in[5];
    const float* w2   = (const float*)d_in[6];
    const float* b2   = (const float*)d_in[7];
    const float* root = (const float*)d_in[8];
    const float* cb   = (const float*)d_in[9];
    const float* lw   = (const float*)d_in[10];
    const float* lb   = (const float*)d_in[11];
    float* out = (float*)d_out;

    build_kernel<<<NBINS, 256>>>(w1, b1, w2, b2);
    hist_kernel<<<NEBLK, 256>>>(ea, bat, w1, b1);
    bin_scan_kernel<<<NBINS, 256>>>(out, lb);
    scatter_kernel<<<NEBLK, 256>>>(ei);
    edge2_kernel<<<NEBLK, 256>>>(x, ei, ea);
    node_kernel<<<(N_NODES + 63) / 64, 256>>>(x, bat, root, cb, lw, out);
}